// round 15
// baseline (speedup 1.0000x reference)
#include <cuda_runtime.h>

#define Bb  2
#define Pp  128
#define Cc  8
#define Hh  16
#define Gg  4
#define Dd  64
#define Ee  1024
#define EKVv 256
#define Tt  1024

// ---------------- scratch (device globals; no allocation allowed) -----------
__device__ __align__(16) float g_q[Bb*Tt*Ee];
__device__ __align__(16) float g_kv[Bb*Tt*2*EKVv];
__device__ __align__(16) float g_tk[Pp*EKVv];
__device__ __align__(16) float g_ck[Cc*EKVv];
__device__ __align__(16) float g_time[Bb*Hh*Tt*Pp];   // reused as split-K partials later
__device__ __align__(16) float g_chan[Bb*Hh*Tt*Cc];
__device__ __align__(16) float g_ao[Bb*Tt*Ee];

// ---------------- packed f32x2 helpers ---------------------------------------
__device__ __forceinline__ unsigned long long dup2(float x) {
    unsigned long long r;
    asm("mov.b64 %0, {%1, %1};" : "=l"(r) : "f"(x));
    return r;
}
__device__ __forceinline__ void fma2(unsigned long long& d,
                                     unsigned long long a, unsigned long long b) {
    asm("fma.rn.f32x2 %0, %1, %2, %0;" : "+l"(d) : "l"(a), "l"(b));
}
__device__ __forceinline__ void unpack2(unsigned long long v, float& lo, float& hi) {
    asm("mov.b64 {%0, %1}, %2;" : "=f"(lo), "=f"(hi) : "l"(v));
}

// ---------------- 64x128 fp32 GEMM tile body (8x8/thread, 128 thr, FMA2) ----
__device__ __forceinline__ void gemm64x128_body(
        const float* __restrict__ A, const float* __restrict__ B,
        float* __restrict__ Cmat, int N, int K, int m0, int n0,
        float (*As)[8][64], float (*Bs)[8][128]) {
    int tid = threadIdx.x;
    int tx = tid & 15, ty = tid >> 4;
    int arow = tid >> 1, akq = (tid & 1) * 4;
    int brow = tid >> 4, bnq = (tid & 15) * 8;

    const float* Aptr = A + (size_t)(m0 + arow) * K + akq;
    const float* Bptr = B + (size_t)brow * N + n0 + bnq;

    unsigned long long acc2[8][4];
#pragma unroll
    for (int i = 0; i < 8; i++)
#pragma unroll
        for (int j = 0; j < 4; j++) acc2[i][j] = 0ull;

    float4 av = *(const float4*)Aptr;
    float4 bv0 = *(const float4*)Bptr;
    float4 bv1 = *(const float4*)(Bptr + 4);
    As[0][akq + 0][arow] = av.x;
    As[0][akq + 1][arow] = av.y;
    As[0][akq + 2][arow] = av.z;
    As[0][akq + 3][arow] = av.w;
    *(float4*)&Bs[0][brow][bnq]     = bv0;
    *(float4*)&Bs[0][brow][bnq + 4] = bv1;
    __syncthreads();

    int NT = K >> 3;    // NOTE: K here is the *loop extent*; Aptr strides use ldA passed as K
    int cur = 0;
    for (int kt = 0; kt < NT; kt++) {
        if (kt + 1 < NT) {
            av  = *(const float4*)(Aptr + (kt + 1) * 8);
            bv0 = *(const float4*)(Bptr + (size_t)(kt + 1) * 8 * N);
            bv1 = *(const float4*)(Bptr + (size_t)(kt + 1) * 8 * N + 4);
        }
#pragma unroll
        for (int k = 0; k < 8; k++) {
            float4 a0 = *(const float4*)&As[cur][k][ty * 8];
            float4 a1 = *(const float4*)&As[cur][k][ty * 8 + 4];
            ulonglong2 bl0 = *(const ulonglong2*)&Bs[cur][k][tx * 8];
            ulonglong2 bl1 = *(const ulonglong2*)&Bs[cur][k][tx * 8 + 4];
            float ra[8] = {a0.x, a0.y, a0.z, a0.w, a1.x, a1.y, a1.z, a1.w};
            unsigned long long rb2[4] = {bl0.x, bl0.y, bl1.x, bl1.y};
#pragma unroll
            for (int i = 0; i < 8; i++) {
                unsigned long long a2 = dup2(ra[i]);
#pragma unroll
                for (int j = 0; j < 4; j++) fma2(acc2[i][j], a2, rb2[j]);
            }
        }
        if (kt + 1 < NT) {
            int nxt = cur ^ 1;
            As[nxt][akq + 0][arow] = av.x;
            As[nxt][akq + 1][arow] = av.y;
            As[nxt][akq + 2][arow] = av.z;
            As[nxt][akq + 3][arow] = av.w;
            *(float4*)&Bs[nxt][brow][bnq]     = bv0;
            *(float4*)&Bs[nxt][brow][bnq + 4] = bv1;
            __syncthreads();
            cur = nxt;
        }
    }

#pragma unroll
    for (int i = 0; i < 8; i++) {
        float* crow = Cmat + (size_t)(m0 + ty * 8 + i) * N + n0 + tx * 8;
        *(ulonglong2*)crow       = make_ulonglong2(acc2[i][0], acc2[i][1]);
        *(ulonglong2*)(crow + 4) = make_ulonglong2(acc2[i][2], acc2[i][3]);
    }
}

// split-K variant: loops kLen columns starting at kOff; ldA = full K of A.
__device__ __forceinline__ void gemm64x128_splitk_body(
        const float* __restrict__ A, const float* __restrict__ B,
        float* __restrict__ Cmat, int N, int ldA, int kOff, int kLen,
        int m0, int n0, float (*As)[8][64], float (*Bs)[8][128]) {
    int tid = threadIdx.x;
    int tx = tid & 15, ty = tid >> 4;
    int arow = tid >> 1, akq = (tid & 1) * 4;
    int brow = tid >> 4, bnq = (tid & 15) * 8;

    const float* Aptr = A + (size_t)(m0 + arow) * ldA + kOff + akq;
    const float* Bptr = B + (size_t)(kOff + brow) * N + n0 + bnq;

    unsigned long long acc2[8][4];
#pragma unroll
    for (int i = 0; i < 8; i++)
#pragma unroll
        for (int j = 0; j < 4; j++) acc2[i][j] = 0ull;

    float4 av = *(const float4*)Aptr;
    float4 bv0 = *(const float4*)Bptr;
    float4 bv1 = *(const float4*)(Bptr + 4);
    As[0][akq + 0][arow] = av.x;
    As[0][akq + 1][arow] = av.y;
    As[0][akq + 2][arow] = av.z;
    As[0][akq + 3][arow] = av.w;
    *(float4*)&Bs[0][brow][bnq]     = bv0;
    *(float4*)&Bs[0][brow][bnq + 4] = bv1;
    __syncthreads();

    int NT = kLen >> 3;
    int cur = 0;
    for (int kt = 0; kt < NT; kt++) {
        if (kt + 1 < NT) {
            av  = *(const float4*)(Aptr + (kt + 1) * 8);
            bv0 = *(const float4*)(Bptr + (size_t)(kt + 1) * 8 * N);
            bv1 = *(const float4*)(Bptr + (size_t)(kt + 1) * 8 * N + 4);
        }
#pragma unroll
        for (int k = 0; k < 8; k++) {
            float4 a0 = *(const float4*)&As[cur][k][ty * 8];
            float4 a1 = *(const float4*)&As[cur][k][ty * 8 + 4];
            ulonglong2 bl0 = *(const ulonglong2*)&Bs[cur][k][tx * 8];
            ulonglong2 bl1 = *(const ulonglong2*)&Bs[cur][k][tx * 8 + 4];
            float ra[8] = {a0.x, a0.y, a0.z, a0.w, a1.x, a1.y, a1.z, a1.w};
            unsigned long long rb2[4] = {bl0.x, bl0.y, bl1.x, bl1.y};
#pragma unroll
            for (int i = 0; i < 8; i++) {
                unsigned long long a2 = dup2(ra[i]);
#pragma unroll
                for (int j = 0; j < 4; j++) fma2(acc2[i][j], a2, rb2[j]);
            }
        }
        if (kt + 1 < NT) {
            int nxt = cur ^ 1;
            As[nxt][akq + 0][arow] = av.x;
            As[nxt][akq + 1][arow] = av.y;
            As[nxt][akq + 2][arow] = av.z;
            As[nxt][akq + 3][arow] = av.w;
            *(float4*)&Bs[nxt][brow][bnq]     = bv0;
            *(float4*)&Bs[nxt][brow][bnq + 4] = bv1;
            __syncthreads();
            cur = nxt;
        }
    }

#pragma unroll
    for (int i = 0; i < 8; i++) {
        float* crow = Cmat + (size_t)(m0 + ty * 8 + i) * N + n0 + tx * 8;
        *(ulonglong2*)crow       = make_ulonglong2(acc2[i][0], acc2[i][1]);
        *(ulonglong2*)(crow + 4) = make_ulonglong2(acc2[i][2], acc2[i][3]);
    }
}

// ---------------- skinny row GEMM: split-K 2 within 128 threads --------------
// C[m, n0:+64]; tid: n = n0 + (tid&63), kc = tid>>6.
__device__ __forceinline__ void skinny_body(
        const float* __restrict__ A, const float* __restrict__ B,
        float* __restrict__ C, int N, int K, int m, int n0) {
    __shared__ float red[64];
    int t = threadIdx.x;
    int n = n0 + (t & 63);
    int kc = t >> 6;
    int kh = K >> 1;
    const float* a = A + (size_t)m * K + kc * kh;
    const float* b = B + (size_t)(kc * kh) * N + n;
    float acc = 0.f;
#pragma unroll 8
    for (int k = 0; k < kh; k++) acc += a[k] * b[(size_t)k * N];
    if (kc) red[t & 63] = acc;
    __syncthreads();
    if (!kc) C[(size_t)m * N + n] = acc + red[t & 63];
}

// ---------------- one launch for ALL projections ------------------------------
// blocks: [0,256) q | [256,384) kv | [384,896) tk | [896,928) ck
__global__ __launch_bounds__(128) void mega_gemm(
        const float* __restrict__ hs, const float* __restrict__ Wq,
        const float* __restrict__ Wkv,
        const float* __restrict__ pe, const float* __restrict__ Wpos,
        const float* __restrict__ ce, const float* __restrict__ Wchan,
        float* __restrict__ q, float* __restrict__ kv,
        float* __restrict__ tk, float* __restrict__ ck) {
    __shared__ float As[2][8][64];
    __shared__ float Bs[2][8][128];
    int blk = blockIdx.x;
    if (blk < 256) {
        gemm64x128_body(hs, Wq, q, Ee, Ee, (blk >> 3) * 64, (blk & 7) * 128, As, Bs);
    } else if (blk < 384) {
        int b = blk - 256;
        gemm64x128_body(hs, Wkv, kv, 2 * EKVv, Ee, (b >> 2) * 64, (b & 3) * 128, As, Bs);
    } else if (blk < 896) {
        int b = blk - 384;
        skinny_body(pe, Wpos, tk, EKVv, Ee, b >> 2, (b & 3) * 64);
    } else {
        int b = blk - 896;
        skinny_body(ce, Wchan, ck, EKVv, Ee, b >> 2, (b & 3) * 64);
    }
}

// ---------------- out-proj: split-K=2 + add ----------------------------------
__global__ __launch_bounds__(128) void sgemm_splitk(
        const float* __restrict__ A, const float* __restrict__ B,
        float* __restrict__ P0, float* __restrict__ P1) {
    __shared__ float As[2][8][64];
    __shared__ float Bs[2][8][128];
    int kc = blockIdx.z;
    float* P = kc ? P1 : P0;
    gemm64x128_splitk_body(A, B, P, Ee, Ee, kc * (Ee / 2), Ee / 2,
                           blockIdx.y * 64, blockIdx.x * 128, As, Bs);
}

__global__ __launch_bounds__(256) void splitk_add(
        const float* __restrict__ P0, const float* __restrict__ P1,
        float* __restrict__ out) {
    int i = blockIdx.x * 256 + threadIdx.x;
    float4 a = ((const float4*)P0)[i];
    float4 b = ((const float4*)P1)[i];
    ((float4*)out)[i] = make_float4(a.x + b.x, a.y + b.y, a.z + b.z, a.w + b.w);
}

// ---------------- merged time_att + chan_att ---------------------------------
__global__ __launch_bounds__(256) void rel_att_kernel(
        const float* __restrict__ q, const float* __restrict__ bias) {
    __shared__ float qs[32][65];
    __shared__ float ks[128][64];
    int blk = blockIdx.x;
    int tid = threadIdx.x;
    if (blk < 1024) {
        int bh = blk & 31;
        int b = bh / Hh, h = bh % Hh, kvh = h / Gg;
        int t0 = (blk >> 5) * 32;
        for (int i = tid; i < 32 * 64; i += 256) {
            int r = i >> 6, d = i & 63;
            qs[r][d] = q[((size_t)(b * Tt + t0 + r)) * Ee + h * Dd + d]
                     + bias[EKVv + kvh * Dd + d];
        }
        for (int i = tid; i < 128 * 64; i += 256) {
            int p = i >> 6, d = i & 63;
            ks[p][d] = g_tk[p * EKVv + kvh * Dd + d];
        }
        __syncthreads();
        int r = tid & 31;
        int pb = (tid >> 5) * 16;
        float acc[16];
#pragma unroll
        for (int j = 0; j < 16; j++) acc[j] = 0.f;
        for (int d = 0; d < 64; d++) {
            float qv = qs[r][d];
#pragma unroll
            for (int j = 0; j < 16; j++) acc[j] += qv * ks[pb + j][d];
        }
        float* dst = g_time + ((size_t)bh * Tt + t0 + r) * Pp + pb;
#pragma unroll
        for (int j = 0; j < 16; j++) dst[j] = acc[j];
    } else {
        int bc = blk - 1024;
        int bh = bc & 31;
        int b = bh / Hh, h = bh % Hh, kvh = h / Gg;
        int t0 = (bc >> 5) * 32;
        for (int i = tid; i < 32 * 64; i += 256) {
            int r = i >> 6, d = i & 63;
            qs[r][d] = q[((size_t)(b * Tt + t0 + r)) * Ee + h * Dd + d]
                     + bias[2 * EKVv + kvh * Dd + d];
        }
        for (int i = tid; i < 8 * 64; i += 256) {
            int c = i >> 6, d = i & 63;
            ks[c][d] = g_ck[c * EKVv + kvh * Dd + d];
        }
        __syncthreads();
        int r = tid >> 3, c = tid & 7;
        float acc = 0.f;
#pragma unroll
        for (int d = 0; d < 64; d++) acc += qs[r][d] * ks[c][d];
        g_chan[((size_t)bh * Tt + t0 + r) * Cc + c] = acc;
    }
}

// ---------------- attention core: one block per (b, h, pt) -------------------
__global__ __launch_bounds__(256) void attn_kernel(
        const float* __restrict__ q, const float* __restrict__ bias) {
    __shared__ float qg[8][68];
    __shared__ __align__(16) float lgT[1024][8];
    __shared__ float rinv[8];
    __shared__ __align__(16) float upool[128 * 68];
    float (*gks)[68] = (float(*)[68])upool;
    float (*sred)[8][64] = (float(*)[8][64])upool;

    int blk = blockIdx.x;
    int pt = (Pp - 1) - (blk % Pp);
    int h  = (blk / Pp) % Hh;
    int b  = blk / (Pp * Hh);
    int kvh = h / Gg;
    int tid = threadIdx.x;
    int t0 = pt * Cc;

    for (int i = tid; i < 8 * 64; i += 256) {
        int c = i >> 6, d = i & 63;
        qg[c][d] = q[((size_t)(b * Tt + t0 + c)) * Ee + h * Dd + d]
                 + bias[kvh * Dd + d];
    }
    __syncthreads();

    int S = (pt + 1) * Cc;
    const float* tbase = g_time + (size_t)(b * Hh + h) * Tt * Pp;
    const float* cbase = g_chan + (size_t)(b * Hh + h) * Tt * Cc;

    for (int s0 = tid; s0 < S; s0 += 256) {
        int ps = s0 >> 3, cs = s0 & 7;
        float vals[8];
#pragma unroll
        for (int c = 0; c < 8; c++) {
            int t = t0 + c;
            unsigned m = (unsigned)(t + 1) * Pp + ps;
            unsigned i2 = m / (Tt + 1);
            float tv = 0.f;
            if (m - i2 * (Tt + 1) != 0) tv = tbase[m - i2 - 1];
            int dc = c - cs; dc = dc < 0 ? -dc : dc;
            vals[c] = tv + cbase[t * Cc + (Cc - 1 - dc)];
        }
        *(float4*)&lgT[s0][0] = make_float4(vals[0], vals[1], vals[2], vals[3]);
        *(float4*)&lgT[s0][4] = make_float4(vals[4], vals[5], vals[6], vals[7]);
    }
    __syncthreads();

    int gLow = (pt == Pp - 1) ? 0 : ((pt > 10 ? pt - 10 : 0) * Cc);
    for (int sb = gLow; sb < S; sb += 128) {
        int rows = min(128, S - sb);
        for (int i = tid; i < rows * 16; i += 256) {
            int r = i >> 4, u = i & 15;
            const float4* src = (const float4*)(g_kv
                + ((size_t)(b * Tt + sb + r)) * (2 * EKVv) + kvh * Dd);
            *(float4*)&gks[r][u * 4] = src[u];
        }
        __syncthreads();
        for (int idx = tid; idx < rows * 8; idx += 256) {
            int r = idx >> 3, c = idx & 7;
            float acc = 0.f;
#pragma unroll
            for (int d4 = 0; d4 < 16; d4++) {
                float4 gv = *(const float4*)&gks[r][d4 * 4];
                float4 qv = *(const float4*)&qg[c][d4 * 4];
                acc += qv.x * gv.x + qv.y * gv.y + qv.z * gv.z + qv.w * gv.w;
            }
            lgT[sb + r][c] += acc;
        }
        __syncthreads();
    }

    int w = tid >> 5, lane = tid & 31;
    {
        float mx = -1e30f;
        for (int s = lane; s < S; s += 32) mx = fmaxf(mx, lgT[s][w] * 0.125f);
#pragma unroll
        for (int o = 16; o > 0; o >>= 1)
            mx = fmaxf(mx, __shfl_xor_sync(0xffffffffu, mx, o));
        float sum = 0.f;
        for (int s = lane; s < S; s += 32) {
            float e = __expf(lgT[s][w] * 0.125f - mx);
            lgT[s][w] = e;
            sum += e;
        }
#pragma unroll
        for (int o = 16; o > 0; o >>= 1)
            sum += __shfl_xor_sync(0xffffffffu, sum, o);
        if (lane == 0) rinv[w] = 1.f / sum;
    }
    __syncthreads();

    {
        int dp = (tid & 31) * 2;
        int sg = tid >> 5;
        const float* vbase = g_kv + (size_t)b * Tt * (2 * EKVv) + EKVv
                           + kvh * Dd + dp;
        unsigned long long accp[2][4];
#pragma unroll
        for (int xy = 0; xy < 2; xy++)
#pragma unroll
            for (int j = 0; j < 4; j++) accp[xy][j] = 0ull;
        for (int s = sg; s < S; s += 8) {
            float2 vv = *(const float2*)(vbase + (size_t)s * (2 * EKVv));
            unsigned long long vx = dup2(vv.x), vy = dup2(vv.y);
            ulonglong2 wA = *(const ulonglong2*)&lgT[s][0];
            ulonglong2 wB = *(const ulonglong2*)&lgT[s][4];
            fma2(accp[0][0], wA.x, vx); fma2(accp[1][0], wA.x, vy);
            fma2(accp[0][1], wA.y, vx); fma2(accp[1][1], wA.y, vy);
            fma2(accp[0][2], wB.x, vx); fma2(accp[1][2], wB.x, vy);
            fma2(accp[0][3], wB.y, vx); fma2(accp[1][3], wB.y, vy);
        }
#pragma unroll
        for (int j = 0; j < 4; j++) {
            float x0, x1, y0, y1;
            unpack2(accp[0][j], x0, x1);
            unpack2(accp[1][j], y0, y1);
            sred[sg][2 * j + 0][dp]     = x0;
            sred[sg][2 * j + 1][dp]     = x1;
            sred[sg][2 * j + 0][dp + 1] = y0;
            sred[sg][2 * j + 1][dp + 1] = y1;
        }
    }
    __syncthreads();
    for (int i = tid; i < 512; i += 256) {
        int c = i >> 6, dd = i & 63;
        float o = ((sred[0][c][dd] + sred[1][c][dd])
                 + (sred[2][c][dd] + sred[3][c][dd]))
                + ((sred[4][c][dd] + sred[5][c][dd])
                 + (sred[6][c][dd] + sred[7][c][dd]));
        g_ao[((size_t)(b * Tt + t0 + c)) * Ee + h * Dd + dd] = o * rinv[c];
    }
}

// ---------------- launch ----------------------------------------------------
extern "C" void kernel_launch(void* const* d_in, const int* in_sizes, int n_in,
                              void* d_out, int out_size) {
    const float* hs    = (const float*)d_in[0];
    const float* pe    = (const float*)d_in[1];
    const float* ce    = (const float*)d_in[2];
    const float* Wq    = (const float*)d_in[3];
    const float* Wkv   = (const float*)d_in[4];
    const float* Wpos  = (const float*)d_in[5];
    const float* Wchan = (const float*)d_in[6];
    const float* Wproj = (const float*)d_in[7];
    const float* bias  = (const float*)d_in[8];

    float *q, *kv, *tk, *ck, *ao, *tm;
    cudaGetSymbolAddress((void**)&q,  g_q);
    cudaGetSymbolAddress((void**)&kv, g_kv);
    cudaGetSymbolAddress((void**)&tk, g_tk);
    cudaGetSymbolAddress((void**)&ck, g_ck);
    cudaGetSymbolAddress((void**)&ao, g_ao);
    cudaGetSymbolAddress((void**)&tm, g_time);

    // all projections in one chip-filling launch
    mega_gemm<<<928, 128>>>(hs, Wq, Wkv, pe, Wpos, ce, Wchan, q, kv, tk, ck);

    // relative logits (time + chan merged)
    rel_att_kernel<<<2048, 256>>>(q, bias);

    // attention core
    attn_kernel<<<Bb * Hh * Pp, 256>>>(q, bias);

    // output projection -> d_out (split-K=2; partials reuse dead g_time)
    float* P0 = tm;
    float* P1 = tm + (size_t)Bb * Tt * Ee;   // g_time has 16M floats >= 2 x 2M
    sgemm_splitk<<<dim3(Ee / 128, (Bb * Tt) / 64, 2), 128>>>(ao, Wproj, P0, P1);
    splitk_add<<<(Bb * Tt * Ee) / (256 * 4), 256>>>(P0, P1, (float*)d_out);
}